// round 9
// baseline (speedup 1.0000x reference)
#include <cuda_runtime.h>
#include <cuda_bf16.h>
#include <math.h>

#define Dn   64
#define Rn   4
#define NMAX 100000
#define EMAX 1200000
#define SEGS (NMAX * Rn)
#define BSTR 68    // highway weight stride (2q perm): banks 8q+g -> conflict-free
#define CBSTR 66   // conv weight stride (4q perm): banks 8q+2i+g -> conflict-free

// ---------------- scratch ----------------
__device__ int   g_deg[SEGS];
__device__ int   g_off[SEGS + 1];
__device__ int   g_cur[SEGS];
__device__ int   g_srcs[EMAX];
__device__ int   g_part[512];
__device__ __nv_bfloat162 g_S[(size_t)SEGS * (Dn / 2)];   // per-(node,rel) MEAN, bf16
__device__ __nv_bfloat162 g_xb[(size_t)NMAX * (Dn / 2)];  // bf16 mirror of x (gather path)
__device__ __nv_bfloat162 g_g1b[(size_t)NMAX * (Dn / 2)]; // bf16 mirror of g1 (gather path)
__device__ float g_h1[(size_t)NMAX * Dn];
__device__ float g_g1[(size_t)NMAX * Dn];
__device__ float g_h2[(size_t)NMAX * Dn];

__device__ __forceinline__ float sigmoidf_(float v) {
    return 1.0f / (1.0f + __expf(-v));
}

__device__ __forceinline__ unsigned f2tf32(float f) {
    unsigned u;
    asm("cvt.rna.tf32.f32 %0, %1;" : "=r"(u) : "f"(f));
    return u;
}

__device__ __forceinline__ float2 b2f2(unsigned u) {
    __nv_bfloat162 t = *reinterpret_cast<__nv_bfloat162*>(&u);
    return __bfloat1622float2(t);
}

__device__ __forceinline__ void mma_tf32(float d[4], const unsigned a[4], const unsigned b[2]) {
    asm volatile("mma.sync.aligned.m16n8k8.row.col.f32.tf32.tf32.f32 "
                 "{%0,%1,%2,%3}, {%4,%5,%6,%7}, {%8,%9}, {%0,%1,%2,%3};"
                 : "+f"(d[0]), "+f"(d[1]), "+f"(d[2]), "+f"(d[3])
                 : "r"(a[0]), "r"(a[1]), "r"(a[2]), "r"(a[3]), "r"(b[0]), "r"(b[1]));
}

// ---------------- fp32 -> bf16x2 mirror ----------------
__global__ void f2b_kernel(const float* __restrict__ in, __nv_bfloat162* __restrict__ out, int n2) {
    int i = blockIdx.x * 256 + threadIdx.x;
    if (i < n2) {
        float2 v = reinterpret_cast<const float2*>(in)[i];
        out[i] = __float22bfloat162_rn(v);
    }
}

// ---------------- CSR build ----------------
__global__ void zero_deg_kernel() {
    int i = blockIdx.x * blockDim.x + threadIdx.x;
    if (i < SEGS) g_deg[i] = 0;
}

__global__ void hist_kernel(const int* __restrict__ dst, const int* __restrict__ rel, int E) {
    int e = blockIdx.x * blockDim.x + threadIdx.x;
    if (e < E) atomicAdd(&g_deg[dst[e] * Rn + rel[e]], 1);
}

__global__ void __launch_bounds__(1024) scan1_kernel(int n) {
    __shared__ int wsum[32];
    int i = blockIdx.x * 1024 + threadIdx.x;
    int lane = threadIdx.x & 31, wid = threadIdx.x >> 5;
    int v = (i < n) ? g_deg[i] : 0;
    int s = v;
#pragma unroll
    for (int d = 1; d < 32; d <<= 1) {
        int t = __shfl_up_sync(0xffffffffu, s, d);
        if (lane >= d) s += t;
    }
    if (lane == 31) wsum[wid] = s;
    __syncthreads();
    if (wid == 0) {
        int t = wsum[lane];
#pragma unroll
        for (int d = 1; d < 32; d <<= 1) {
            int u = __shfl_up_sync(0xffffffffu, t, d);
            if (lane >= d) t += u;
        }
        wsum[lane] = t;
    }
    __syncthreads();
    int add = (wid > 0) ? wsum[wid - 1] : 0;
    int inc = s + add;
    if (i < n) g_off[i] = inc - v;
    if (threadIdx.x == 1023) g_part[blockIdx.x] = inc;
}

__global__ void __launch_bounds__(512) scan2_kernel(int n) {
    __shared__ int wsum[16];
    int i = threadIdx.x;
    int lane = i & 31, wid = i >> 5;
    int v = (i < n) ? g_part[i] : 0;
    int s = v;
#pragma unroll
    for (int d = 1; d < 32; d <<= 1) {
        int t = __shfl_up_sync(0xffffffffu, s, d);
        if (lane >= d) s += t;
    }
    if (lane == 31) wsum[wid] = s;
    __syncthreads();
    if (wid == 0 && lane < 16) {
        int t = wsum[lane];
#pragma unroll
        for (int d = 1; d < 16; d <<= 1) {
            int u = __shfl_up_sync(0x0000ffffu, t, d);
            if (lane >= d) t += u;
        }
        wsum[lane] = t;
    }
    __syncthreads();
    int add = (wid > 0) ? wsum[wid - 1] : 0;
    if (i < n) g_part[i] = s - v + add;
}

__global__ void scan3_kernel(int n, int E) {
    int i = blockIdx.x * blockDim.x + threadIdx.x;
    if (i < n) {
        int o = g_off[i] + g_part[i >> 10];
        g_off[i] = o;
        g_cur[i] = o;
    }
    if (i == 0) g_off[n] = E;
}

__global__ void scatter_kernel(const int* __restrict__ src, const int* __restrict__ dst,
                               const int* __restrict__ rel, int E) {
    int e = blockIdx.x * blockDim.x + threadIdx.x;
    if (e >= E) return;
    int seg = dst[e] * Rn + rel[e];
    int p = atomicAdd(&g_cur[seg], 1);
    g_srcs[p] = src[e];
}

// ---------------- aggregate: S[seg] = MEAN over edges of xb[src] (bf16 in/out) ----------------
__global__ void __launch_bounds__(256) aggregate_kernel(const __nv_bfloat162* __restrict__ xb) {
    int t = blockIdx.x * 256 + threadIdx.x;
    int seg = t >> 4;
    int lane = t & 15;
    if (seg >= SEGS) return;
    const uint2* rows = reinterpret_cast<const uint2*>(xb);
    int e0 = __ldg(&g_off[seg]);
    int e1 = __ldg(&g_off[seg + 1]);
    float4 acc = make_float4(0.f, 0.f, 0.f, 0.f);
    int e = e0;
    for (; e + 3 < e1; e += 4) {
        int s0 = __ldg(&g_srcs[e]);
        int s1 = __ldg(&g_srcs[e + 1]);
        int s2 = __ldg(&g_srcs[e + 2]);
        int s3 = __ldg(&g_srcs[e + 3]);
        uint2 u0 = __ldg(&rows[(size_t)s0 * 16 + lane]);
        uint2 u1 = __ldg(&rows[(size_t)s1 * 16 + lane]);
        uint2 u2 = __ldg(&rows[(size_t)s2 * 16 + lane]);
        uint2 u3 = __ldg(&rows[(size_t)s3 * 16 + lane]);
        float2 a0 = b2f2(u0.x), b0 = b2f2(u0.y);
        float2 a1 = b2f2(u1.x), b1 = b2f2(u1.y);
        float2 a2 = b2f2(u2.x), b2 = b2f2(u2.y);
        float2 a3 = b2f2(u3.x), b3 = b2f2(u3.y);
        acc.x += (a0.x + a1.x) + (a2.x + a3.x);
        acc.y += (a0.y + a1.y) + (a2.y + a3.y);
        acc.z += (b0.x + b1.x) + (b2.x + b3.x);
        acc.w += (b0.y + b1.y) + (b2.y + b3.y);
    }
    for (; e < e1; e++) {
        int s0 = __ldg(&g_srcs[e]);
        uint2 u0 = __ldg(&rows[(size_t)s0 * 16 + lane]);
        float2 a0 = b2f2(u0.x), b0 = b2f2(u0.y);
        acc.x += a0.x; acc.y += a0.y; acc.z += b0.x; acc.w += b0.y;
    }
    int d = e1 - e0;
    float inv = 1.0f / (float)(d > 1 ? d : 1);
    __nv_bfloat162 p0 = __float22bfloat162_rn(make_float2(acc.x * inv, acc.y * inv));
    __nv_bfloat162 p1 = __float22bfloat162_rn(make_float2(acc.z * inv, acc.w * inv));
    g_S[(size_t)seg * 32 + lane * 2]     = p0;
    g_S[(size_t)seg * 32 + lane * 2 + 1] = p1;
}

// ---------------- conv via tf32 mma: out = sigmoid([S_mean | x] @ W^T + b) ----------------
// 256 threads / 8 warps, 32 nodes per warp. 4-wide k-permutation:
// within a 16-k window, lane quad q owns actual k = 4q..4q+3 (full-sector loads).
__global__ void __launch_bounds__(256)
conv_mma_kernel(const float* __restrict__ xin,
                const __nv_bfloat162* __restrict__ S,
                const float* __restrict__ w,   // [64][256]
                const float* __restrict__ b,
                const float* __restrict__ ws,  // [64][64]
                const float* __restrict__ bs,
                float* __restrict__ out,
                int N) {
    extern __shared__ unsigned smu[];
    unsigned* sw = smu;                           // 320 * CBSTR words
    float* sb = (float*)(smu + 320 * CBSTR);      // 64
    int tid = threadIdx.x;

    for (int idx = tid; idx < Dn * 256; idx += 256) {
        int j = idx >> 8, k = idx & 255;
        sw[k * CBSTR + j] = f2tf32(w[idx]);
    }
    for (int idx = tid; idx < Dn * Dn; idx += 256) {
        int j = idx >> 6, k = idx & 63;
        sw[(256 + k) * CBSTR + j] = f2tf32(ws[idx]);
    }
    if (tid < Dn) sb[tid] = b[tid] + bs[tid];
    __syncthreads();

    int lane = tid & 31, warp = tid >> 5;
    int g = lane >> 2, q = lane & 3;
    int mbase = blockIdx.x * 256 + warp * 32;

    int r0 = mbase + g, r1 = r0 + 8, r2 = r0 + 16, r3 = r0 + 24;
    int cr0 = min(r0, N - 1), cr1 = min(r1, N - 1);
    int cr2 = min(r2, N - 1), cr3 = min(r3, N - 1);

    float acc[2][8][4];
#pragma unroll
    for (int mt = 0; mt < 2; mt++)
#pragma unroll
        for (int n = 0; n < 8; n++)
#pragma unroll
            for (int i = 0; i < 4; i++) acc[mt][n][i] = 0.f;

    const __nv_bfloat162* S0 = S + (size_t)cr0 * 128;
    const __nv_bfloat162* S1 = S + (size_t)cr1 * 128;
    const __nv_bfloat162* S2 = S + (size_t)cr2 * 128;
    const __nv_bfloat162* S3 = S + (size_t)cr3 * 128;

#pragma unroll 2
    for (int kw = 0; kw < 16; kw++) {
        int pi = kw * 8 + 2 * q;     // bf16x2 pair index (8B-aligned)
        uint2 u0 = *reinterpret_cast<const uint2*>(S0 + pi);
        uint2 u1 = *reinterpret_cast<const uint2*>(S1 + pi);
        uint2 u2 = *reinterpret_cast<const uint2*>(S2 + pi);
        uint2 u3 = *reinterpret_cast<const uint2*>(S3 + pi);
        float2 r0p0 = b2f2(u0.x), r0p1 = b2f2(u0.y);
        float2 r1p0 = b2f2(u1.x), r1p1 = b2f2(u1.y);
        float2 r2p0 = b2f2(u2.x), r2p1 = b2f2(u2.y);
        float2 r3p0 = b2f2(u3.x), r3p1 = b2f2(u3.y);
        int ka = kw * 16 + 4 * q;
        const unsigned* w0 = sw + ka * CBSTR + g;
        unsigned A00[4] = { f2tf32(r0p0.x), f2tf32(r1p0.x), f2tf32(r0p0.y), f2tf32(r1p0.y) };
        unsigned A10[4] = { f2tf32(r2p0.x), f2tf32(r3p0.x), f2tf32(r2p0.y), f2tf32(r3p0.y) };
        unsigned A01[4] = { f2tf32(r0p1.x), f2tf32(r1p1.x), f2tf32(r0p1.y), f2tf32(r1p1.y) };
        unsigned A11[4] = { f2tf32(r2p1.x), f2tf32(r3p1.x), f2tf32(r2p1.y), f2tf32(r3p1.y) };
#pragma unroll
        for (int n = 0; n < 8; n++) {
            unsigned b0[2] = { w0[n * 8], w0[CBSTR + n * 8] };
            unsigned b1[2] = { w0[2 * CBSTR + n * 8], w0[3 * CBSTR + n * 8] };
            mma_tf32(acc[0][n], A00, b0);
            mma_tf32(acc[1][n], A10, b0);
            mma_tf32(acc[0][n], A01, b1);
            mma_tf32(acc[1][n], A11, b1);
        }
    }

    const float* X0 = xin + (size_t)cr0 * Dn;
    const float* X1 = xin + (size_t)cr1 * Dn;
    const float* X2 = xin + (size_t)cr2 * Dn;
    const float* X3 = xin + (size_t)cr3 * Dn;
#pragma unroll
    for (int kw = 0; kw < 4; kw++) {
        int ka = kw * 16 + 4 * q;
        float4 x0 = *reinterpret_cast<const float4*>(X0 + ka);
        float4 x1 = *reinterpret_cast<const float4*>(X1 + ka);
        float4 x2 = *reinterpret_cast<const float4*>(X2 + ka);
        float4 x3 = *reinterpret_cast<const float4*>(X3 + ka);
        const unsigned* w0 = sw + (256 + ka) * CBSTR + g;
        unsigned A00[4] = { f2tf32(x0.x), f2tf32(x1.x), f2tf32(x0.y), f2tf32(x1.y) };
        unsigned A10[4] = { f2tf32(x2.x), f2tf32(x3.x), f2tf32(x2.y), f2tf32(x3.y) };
        unsigned A01[4] = { f2tf32(x0.z), f2tf32(x1.z), f2tf32(x0.w), f2tf32(x1.w) };
        unsigned A11[4] = { f2tf32(x2.z), f2tf32(x3.z), f2tf32(x2.w), f2tf32(x3.w) };
#pragma unroll
        for (int n = 0; n < 8; n++) {
            unsigned b0[2] = { w0[n * 8], w0[CBSTR + n * 8] };
            unsigned b1[2] = { w0[2 * CBSTR + n * 8], w0[3 * CBSTR + n * 8] };
            mma_tf32(acc[0][n], A00, b0);
            mma_tf32(acc[1][n], A10, b0);
            mma_tf32(acc[0][n], A01, b1);
            mma_tf32(acc[1][n], A11, b1);
        }
    }

#pragma unroll
    for (int n = 0; n < 8; n++) {
        int col = n * 8 + 2 * q;
        float b0v = sb[col], b1v = sb[col + 1];
        if (r0 < N) {
            float2 o = { sigmoidf_(acc[0][n][0] + b0v), sigmoidf_(acc[0][n][1] + b1v) };
            *reinterpret_cast<float2*>(out + (size_t)r0 * Dn + col) = o;
        }
        if (r1 < N) {
            float2 o = { sigmoidf_(acc[0][n][2] + b0v), sigmoidf_(acc[0][n][3] + b1v) };
            *reinterpret_cast<float2*>(out + (size_t)r1 * Dn + col) = o;
        }
        if (r2 < N) {
            float2 o = { sigmoidf_(acc[1][n][0] + b0v), sigmoidf_(acc[1][n][1] + b1v) };
            *reinterpret_cast<float2*>(out + (size_t)r2 * Dn + col) = o;
        }
        if (r3 < N) {
            float2 o = { sigmoidf_(acc[1][n][2] + b0v), sigmoidf_(acc[1][n][3] + b1v) };
            *reinterpret_cast<float2*>(out + (size_t)r3 * Dn + col) = o;
        }
    }
}

// ---------------- highway via tf32 mma ----------------
// 256 threads / 8 warps, 16 nodes per warp -> 128 nodes per block.
// Optionally dual-writes a bf16 mirror of the output (gather path for next layer).
__global__ void __launch_bounds__(256)
highway_mma_kernel(const float* __restrict__ h,
                   const float* __restrict__ prev,
                   const float* __restrict__ pw,   // [64][128]
                   const float* __restrict__ pb,
                   const float* __restrict__ tw,   // [64][128]
                   const float* __restrict__ tb,
                   float* __restrict__ out,
                   __nv_bfloat162* __restrict__ outb,
                   int N) {
    extern __shared__ unsigned smu[];
    unsigned* sp = smu;                            // 128 * BSTR
    unsigned* st = sp + 128 * BSTR;                // 128 * BSTR
    float* sbp = (float*)(st + 128 * BSTR);        // 64
    float* sbt = sbp + Dn;                         // 64
    int tid = threadIdx.x;

    for (int idx = tid; idx < Dn * 128; idx += 256) {
        int j = idx >> 7, k = idx & 127;
        sp[k * BSTR + j] = f2tf32(pw[idx]);
        st[k * BSTR + j] = f2tf32(tw[idx]);
    }
    if (tid < Dn) { sbp[tid] = pb[tid]; sbt[tid] = tb[tid]; }
    __syncthreads();

    int lane = tid & 31, warp = tid >> 5;
    int g = lane >> 2, q = lane & 3;
    int mbase = blockIdx.x * 128 + warp * 16;

    int r0 = mbase + g, r1 = r0 + 8;
    int cr0 = min(r0, N - 1), cr1 = min(r1, N - 1);

    float accP[8][4], accT[8][4];
#pragma unroll
    for (int n = 0; n < 8; n++)
#pragma unroll
        for (int i = 0; i < 4; i++) { accP[n][i] = 0.f; accT[n][i] = 0.f; }

    const float* H0 = h + (size_t)cr0 * Dn;
    const float* H1 = h + (size_t)cr1 * Dn;
    const float* P0 = prev + (size_t)cr0 * Dn;
    const float* P1 = prev + (size_t)cr1 * Dn;

#pragma unroll
    for (int ks = 0; ks < 8; ks++) {
        int ka = ks * 8 + 2 * q;
        float2 s0 = *reinterpret_cast<const float2*>(H0 + ka);
        float2 s1 = *reinterpret_cast<const float2*>(H1 + ka);
        unsigned a[4] = { f2tf32(s0.x), f2tf32(s1.x), f2tf32(s0.y), f2tf32(s1.y) };
        const unsigned* p0 = sp + ka * BSTR + g;
        const unsigned* t0 = st + ka * BSTR + g;
#pragma unroll
        for (int n = 0; n < 8; n++) {
            unsigned bp[2] = { p0[n * 8], p0[BSTR + n * 8] };
            unsigned bt[2] = { t0[n * 8], t0[BSTR + n * 8] };
            mma_tf32(accP[n], a, bp);
            mma_tf32(accT[n], a, bt);
        }
    }
#pragma unroll
    for (int ks = 0; ks < 8; ks++) {
        int ka = ks * 8 + 2 * q;
        float2 s0 = *reinterpret_cast<const float2*>(P0 + ka);
        float2 s1 = *reinterpret_cast<const float2*>(P1 + ka);
        unsigned a[4] = { f2tf32(s0.x), f2tf32(s1.x), f2tf32(s0.y), f2tf32(s1.y) };
        const unsigned* p0 = sp + (64 + ka) * BSTR + g;
        const unsigned* t0 = st + (64 + ka) * BSTR + g;
#pragma unroll
        for (int n = 0; n < 8; n++) {
            unsigned bp[2] = { p0[n * 8], p0[BSTR + n * 8] };
            unsigned bt[2] = { t0[n * 8], t0[BSTR + n * 8] };
            mma_tf32(accP[n], a, bp);
            mma_tf32(accT[n], a, bt);
        }
    }

#pragma unroll
    for (int n = 0; n < 8; n++) {
        int col = n * 8 + 2 * q;
        float bp0 = sbp[col], bp1 = sbp[col + 1];
        float bt0 = sbt[col], bt1 = sbt[col + 1];
        if (r0 < N) {
            float2 hv = *reinterpret_cast<const float2*>(h + (size_t)r0 * Dn + col);
            float pr0 = fmaxf(accP[n][0] + bp0, 0.f);
            float pr1 = fmaxf(accP[n][1] + bp1, 0.f);
            float g0 = sigmoidf_(accT[n][0] + bt0);
            float g1 = sigmoidf_(accT[n][1] + bt1);
            float2 o = { g0 * pr0 + (1.f - g0) * hv.x, g1 * pr1 + (1.f - g1) * hv.y };
            *reinterpret_cast<float2*>(out + (size_t)r0 * Dn + col) = o;
            if (outb) outb[((size_t)r0 * Dn + col) >> 1] = __float22bfloat162_rn(o);
        }
        if (r1 < N) {
            float2 hv = *reinterpret_cast<const float2*>(h + (size_t)r1 * Dn + col);
            float pr0 = fmaxf(accP[n][2] + bp0, 0.f);
            float pr1 = fmaxf(accP[n][3] + bp1, 0.f);
            float g0 = sigmoidf_(accT[n][2] + bt0);
            float g1 = sigmoidf_(accT[n][3] + bt1);
            float2 o = { g0 * pr0 + (1.f - g0) * hv.x, g1 * pr1 + (1.f - g1) * hv.y };
            *reinterpret_cast<float2*>(out + (size_t)r1 * Dn + col) = o;
            if (outb) outb[((size_t)r1 * Dn + col) >> 1] = __float22bfloat162_rn(o);
        }
    }
}

// ---------------- launch ----------------
extern "C" void kernel_launch(void* const* d_in, const int* in_sizes, int n_in,
                              void* d_out, int out_size) {
    const float* x    = (const float*)d_in[0];
    const int*   src  = (const int*)d_in[1];
    const int*   dst  = (const int*)d_in[2];
    const int*   rel  = (const int*)d_in[3];
    const float* c1w  = (const float*)d_in[4];
    const float* c1b  = (const float*)d_in[5];
    const float* c1ws = (const float*)d_in[6];
    const float* c1bs = (const float*)d_in[7];
    const float* h1pw = (const float*)d_in[8];
    const float* h1pb = (const float*)d_in[9];
    const float* h1tw = (const float*)d_in[10];
    const float* h1tb = (const float*)d_in[11];
    const float* c2w  = (const float*)d_in[12];
    const float* c2b  = (const float*)d_in[13];
    const float* c2ws = (const float*)d_in[14];
    const float* c2bs = (const float*)d_in[15];
    const float* h2pw = (const float*)d_in[16];
    const float* h2pb = (const float*)d_in[17];
    const float* h2tw = (const float*)d_in[18];
    const float* h2tb = (const float*)d_in[19];
    float* out = (float*)d_out;

    int N = in_sizes[0] / Dn;
    int E = in_sizes[1];

    __nv_bfloat162 *Sp, *xbp, *g1bp;
    float *h1p, *g1p, *h2p;
    cudaGetSymbolAddress((void**)&Sp, g_S);
    cudaGetSymbolAddress((void**)&xbp, g_xb);
    cudaGetSymbolAddress((void**)&g1bp, g_g1b);
    cudaGetSymbolAddress((void**)&h1p, g_h1);
    cudaGetSymbolAddress((void**)&g1p, g_g1);
    cudaGetSymbolAddress((void**)&h2p, g_h2);

    const int convSmem = 320 * CBSTR * 4 + 64 * 4;
    const int hwSmem   = 2 * 128 * BSTR * 4 + 128 * 4;
    cudaFuncSetAttribute(conv_mma_kernel, cudaFuncAttributeMaxDynamicSharedMemorySize, convSmem);
    cudaFuncSetAttribute(highway_mma_kernel, cudaFuncAttributeMaxDynamicSharedMemorySize, hwSmem);

    int convGrid = (N + 255) / 256;
    int hwGrid   = (N + 127) / 128;
    int scanBlocks = (SEGS + 1023) / 1024;

    // ---- bf16 mirror of x + CSR build (graph identical in both layers) ----
    f2b_kernel<<<(N * 32 + 255) / 256, 256>>>(x, xbp, N * 32);
    zero_deg_kernel<<<(SEGS + 255) / 256, 256>>>();
    hist_kernel<<<(E + 255) / 256, 256>>>(dst, rel, E);
    scan1_kernel<<<scanBlocks, 1024>>>(SEGS);
    scan2_kernel<<<1, 512>>>(scanBlocks);
    scan3_kernel<<<(SEGS + 255) / 256, 256>>>(SEGS, E);
    scatter_kernel<<<(E + 255) / 256, 256>>>(src, dst, rel, E);

    int aggGrid = SEGS / 16;

    // ---- layer 1 ----
    aggregate_kernel<<<aggGrid, 256>>>(xbp);
    conv_mma_kernel<<<convGrid, 256, convSmem>>>(x, Sp, c1w, c1b, c1ws, c1bs, h1p, N);
    highway_mma_kernel<<<hwGrid, 256, hwSmem>>>(h1p, x, h1pw, h1pb, h1tw, h1tb, g1p, g1bp, N);

    // ---- layer 2 ----
    aggregate_kernel<<<aggGrid, 256>>>(g1bp);
    conv_mma_kernel<<<convGrid, 256, convSmem>>>(g1p, Sp, c2w, c2b, c2ws, c2bs, h2p, N);
    highway_mma_kernel<<<hwGrid, 256, hwSmem>>>(h2p, h1p, h2pw, h2pb, h2tw, h2tb, out, nullptr, N);
}

// round 10
// speedup vs baseline: 1.0607x; 1.0607x over previous
#include <cuda_runtime.h>
#include <cuda_bf16.h>
#include <math.h>

#define Dn   64
#define Rn   4
#define NMAX 100000
#define EMAX 1200000
#define SEGS (NMAX * Rn)
#define BSTR 68   // weight smem stride: banks (2q*68)%32 = 8q -> conflict-free permuted B frags

// ---------------- scratch ----------------
__device__ int   g_deg[SEGS];
__device__ int   g_off[SEGS + 1];
__device__ int   g_cur[SEGS];
__device__ int   g_srcs[EMAX];
__device__ int   g_part[512];
__device__ __nv_bfloat162 g_S[(size_t)SEGS * (Dn / 2)];   // per-(node,rel) MEAN, bf16
__device__ __nv_bfloat162 g_xb[(size_t)NMAX * (Dn / 2)];  // bf16 mirror of x (gather path)
__device__ __nv_bfloat162 g_g1b[(size_t)NMAX * (Dn / 2)]; // bf16 mirror of g1 (gather path)
__device__ float g_h1[(size_t)NMAX * Dn];
__device__ float g_g1[(size_t)NMAX * Dn];
__device__ float g_h2[(size_t)NMAX * Dn];

__device__ __forceinline__ float sigmoidf_(float v) {
    return 1.0f / (1.0f + __expf(-v));
}

__device__ __forceinline__ unsigned f2tf32(float f) {
    unsigned u;
    asm("cvt.rna.tf32.f32 %0, %1;" : "=r"(u) : "f"(f));
    return u;
}

__device__ __forceinline__ float2 b2f2(unsigned u) {
    __nv_bfloat162 t = *reinterpret_cast<__nv_bfloat162*>(&u);
    return __bfloat1622float2(t);
}

__device__ __forceinline__ void mma_tf32(float d[4], const unsigned a[4], const unsigned b[2]) {
    asm volatile("mma.sync.aligned.m16n8k8.row.col.f32.tf32.tf32.f32 "
                 "{%0,%1,%2,%3}, {%4,%5,%6,%7}, {%8,%9}, {%0,%1,%2,%3};"
                 : "+f"(d[0]), "+f"(d[1]), "+f"(d[2]), "+f"(d[3])
                 : "r"(a[0]), "r"(a[1]), "r"(a[2]), "r"(a[3]), "r"(b[0]), "r"(b[1]));
}

// ---------------- fp32 -> bf16x2 mirror ----------------
__global__ void f2b_kernel(const float* __restrict__ in, __nv_bfloat162* __restrict__ out, int n2) {
    int i = blockIdx.x * 256 + threadIdx.x;
    if (i < n2) {
        float2 v = reinterpret_cast<const float2*>(in)[i];
        out[i] = __float22bfloat162_rn(v);
    }
}

// ---------------- CSR build ----------------
__global__ void zero_deg_kernel() {
    int i = blockIdx.x * blockDim.x + threadIdx.x;
    if (i < SEGS) g_deg[i] = 0;
}

__global__ void hist_kernel(const int* __restrict__ dst, const int* __restrict__ rel, int E) {
    int e = blockIdx.x * blockDim.x + threadIdx.x;
    if (e < E) atomicAdd(&g_deg[dst[e] * Rn + rel[e]], 1);
}

__global__ void __launch_bounds__(1024) scan1_kernel(int n) {
    __shared__ int wsum[32];
    int i = blockIdx.x * 1024 + threadIdx.x;
    int lane = threadIdx.x & 31, wid = threadIdx.x >> 5;
    int v = (i < n) ? g_deg[i] : 0;
    int s = v;
#pragma unroll
    for (int d = 1; d < 32; d <<= 1) {
        int t = __shfl_up_sync(0xffffffffu, s, d);
        if (lane >= d) s += t;
    }
    if (lane == 31) wsum[wid] = s;
    __syncthreads();
    if (wid == 0) {
        int t = wsum[lane];
#pragma unroll
        for (int d = 1; d < 32; d <<= 1) {
            int u = __shfl_up_sync(0xffffffffu, t, d);
            if (lane >= d) t += u;
        }
        wsum[lane] = t;
    }
    __syncthreads();
    int add = (wid > 0) ? wsum[wid - 1] : 0;
    int inc = s + add;
    if (i < n) g_off[i] = inc - v;
    if (threadIdx.x == 1023) g_part[blockIdx.x] = inc;
}

__global__ void __launch_bounds__(512) scan2_kernel(int n) {
    __shared__ int wsum[16];
    int i = threadIdx.x;
    int lane = i & 31, wid = i >> 5;
    int v = (i < n) ? g_part[i] : 0;
    int s = v;
#pragma unroll
    for (int d = 1; d < 32; d <<= 1) {
        int t = __shfl_up_sync(0xffffffffu, s, d);
        if (lane >= d) s += t;
    }
    if (lane == 31) wsum[wid] = s;
    __syncthreads();
    if (wid == 0 && lane < 16) {
        int t = wsum[lane];
#pragma unroll
        for (int d = 1; d < 16; d <<= 1) {
            int u = __shfl_up_sync(0x0000ffffu, t, d);
            if (lane >= d) t += u;
        }
        wsum[lane] = t;
    }
    __syncthreads();
    int add = (wid > 0) ? wsum[wid - 1] : 0;
    if (i < n) g_part[i] = s - v + add;
}

__global__ void scan3_kernel(int n, int E) {
    int i = blockIdx.x * blockDim.x + threadIdx.x;
    if (i < n) {
        int o = g_off[i] + g_part[i >> 10];
        g_off[i] = o;
        g_cur[i] = o;
    }
    if (i == 0) g_off[n] = E;
}

__global__ void scatter_kernel(const int* __restrict__ src, const int* __restrict__ dst,
                               const int* __restrict__ rel, int E) {
    int e = blockIdx.x * blockDim.x + threadIdx.x;
    if (e >= E) return;
    int seg = dst[e] * Rn + rel[e];
    int p = atomicAdd(&g_cur[seg], 1);
    g_srcs[p] = src[e];
}

// ---------------- aggregate: S[seg] = MEAN over edges of xb[src] ----------------
// 8 lanes per segment, uint4 (16B = 8 bf16) per lane: half the LDG count of fp32/16-lane.
__global__ void __launch_bounds__(256) aggregate_kernel(const __nv_bfloat162* __restrict__ xb) {
    int t = blockIdx.x * 256 + threadIdx.x;
    int seg = t >> 3;
    int lane = t & 7;
    if (seg >= SEGS) return;
    const uint4* rows = reinterpret_cast<const uint4*>(xb);
    int e0 = __ldg(&g_off[seg]);
    int e1 = __ldg(&g_off[seg + 1]);
    float a0 = 0.f, a1 = 0.f, a2 = 0.f, a3 = 0.f;
    float a4 = 0.f, a5 = 0.f, a6 = 0.f, a7 = 0.f;
    int e = e0;
    for (; e + 3 < e1; e += 4) {
        int s0 = __ldg(&g_srcs[e]);
        int s1 = __ldg(&g_srcs[e + 1]);
        int s2 = __ldg(&g_srcs[e + 2]);
        int s3 = __ldg(&g_srcs[e + 3]);
        uint4 u0 = __ldg(&rows[(size_t)s0 * 8 + lane]);
        uint4 u1 = __ldg(&rows[(size_t)s1 * 8 + lane]);
        uint4 u2 = __ldg(&rows[(size_t)s2 * 8 + lane]);
        uint4 u3 = __ldg(&rows[(size_t)s3 * 8 + lane]);
        float2 p;
        p = b2f2(u0.x); a0 += p.x; a1 += p.y;
        p = b2f2(u0.y); a2 += p.x; a3 += p.y;
        p = b2f2(u0.z); a4 += p.x; a5 += p.y;
        p = b2f2(u0.w); a6 += p.x; a7 += p.y;
        p = b2f2(u1.x); a0 += p.x; a1 += p.y;
        p = b2f2(u1.y); a2 += p.x; a3 += p.y;
        p = b2f2(u1.z); a4 += p.x; a5 += p.y;
        p = b2f2(u1.w); a6 += p.x; a7 += p.y;
        p = b2f2(u2.x); a0 += p.x; a1 += p.y;
        p = b2f2(u2.y); a2 += p.x; a3 += p.y;
        p = b2f2(u2.z); a4 += p.x; a5 += p.y;
        p = b2f2(u2.w); a6 += p.x; a7 += p.y;
        p = b2f2(u3.x); a0 += p.x; a1 += p.y;
        p = b2f2(u3.y); a2 += p.x; a3 += p.y;
        p = b2f2(u3.z); a4 += p.x; a5 += p.y;
        p = b2f2(u3.w); a6 += p.x; a7 += p.y;
    }
    for (; e < e1; e++) {
        int s0 = __ldg(&g_srcs[e]);
        uint4 u0 = __ldg(&rows[(size_t)s0 * 8 + lane]);
        float2 p;
        p = b2f2(u0.x); a0 += p.x; a1 += p.y;
        p = b2f2(u0.y); a2 += p.x; a3 += p.y;
        p = b2f2(u0.z); a4 += p.x; a5 += p.y;
        p = b2f2(u0.w); a6 += p.x; a7 += p.y;
    }
    int d = e1 - e0;
    float inv = 1.0f / (float)(d > 1 ? d : 1);
    uint4 o;
    __nv_bfloat162 t0 = __float22bfloat162_rn(make_float2(a0 * inv, a1 * inv));
    __nv_bfloat162 t1 = __float22bfloat162_rn(make_float2(a2 * inv, a3 * inv));
    __nv_bfloat162 t2 = __float22bfloat162_rn(make_float2(a4 * inv, a5 * inv));
    __nv_bfloat162 t3 = __float22bfloat162_rn(make_float2(a6 * inv, a7 * inv));
    o.x = *reinterpret_cast<unsigned*>(&t0);
    o.y = *reinterpret_cast<unsigned*>(&t1);
    o.z = *reinterpret_cast<unsigned*>(&t2);
    o.w = *reinterpret_cast<unsigned*>(&t3);
    reinterpret_cast<uint4*>(g_S)[(size_t)seg * 8 + lane] = o;
}

// ---------------- conv via tf32 mma: out = sigmoid([S_mean | x] @ W^T + b) ----------------
// 256 threads / 8 warps, 32 nodes per warp -> 256 nodes per block.  (R8-proven version)
__global__ void __launch_bounds__(256)
conv_mma_kernel(const float* __restrict__ xin,
                const __nv_bfloat162* __restrict__ S,
                const float* __restrict__ w,   // [64][256]
                const float* __restrict__ b,
                const float* __restrict__ ws,  // [64][64]
                const float* __restrict__ bs,
                float* __restrict__ out,
                int N) {
    extern __shared__ unsigned smu[];
    unsigned* sw = smu;                           // 320 * BSTR words
    float* sb = (float*)(smu + 320 * BSTR);       // 64
    int tid = threadIdx.x;

    for (int idx = tid; idx < Dn * 256; idx += 256) {
        int j = idx >> 8, k = idx & 255;
        sw[k * BSTR + j] = f2tf32(w[idx]);
    }
    for (int idx = tid; idx < Dn * Dn; idx += 256) {
        int j = idx >> 6, k = idx & 63;
        sw[(256 + k) * BSTR + j] = f2tf32(ws[idx]);
    }
    if (tid < Dn) sb[tid] = b[tid] + bs[tid];
    __syncthreads();

    int lane = tid & 31, warp = tid >> 5;
    int g = lane >> 2, q = lane & 3;
    int mbase = blockIdx.x * 256 + warp * 32;

    int r0 = mbase + g, r1 = r0 + 8, r2 = r0 + 16, r3 = r0 + 24;
    int cr0 = min(r0, N - 1), cr1 = min(r1, N - 1);
    int cr2 = min(r2, N - 1), cr3 = min(r3, N - 1);

    float acc[2][8][4];
#pragma unroll
    for (int mt = 0; mt < 2; mt++)
#pragma unroll
        for (int n = 0; n < 8; n++)
#pragma unroll
            for (int i = 0; i < 4; i++) acc[mt][n][i] = 0.f;

    const __nv_bfloat162* S0 = S + (size_t)cr0 * 128;
    const __nv_bfloat162* S1 = S + (size_t)cr1 * 128;
    const __nv_bfloat162* S2 = S + (size_t)cr2 * 128;
    const __nv_bfloat162* S3 = S + (size_t)cr3 * 128;

#pragma unroll 4
    for (int ks = 0; ks < 32; ks++) {
        int pi = ks * 4 + q;   // bf16x2 pair index: elements 2q, 2q+1 of k-block
        float2 s0 = __bfloat1622float2(S0[pi]);
        float2 s1 = __bfloat1622float2(S1[pi]);
        float2 s2 = __bfloat1622float2(S2[pi]);
        float2 s3 = __bfloat1622float2(S3[pi]);
        unsigned a0[4] = { f2tf32(s0.x), f2tf32(s1.x), f2tf32(s0.y), f2tf32(s1.y) };
        unsigned a1[4] = { f2tf32(s2.x), f2tf32(s3.x), f2tf32(s2.y), f2tf32(s3.y) };
        const unsigned* w0 = sw + (ks * 8 + 2 * q) * BSTR + g;
#pragma unroll
        for (int n = 0; n < 8; n++) {
            unsigned bb[2] = { w0[n * 8], w0[BSTR + n * 8] };
            mma_tf32(acc[0][n], a0, bb);
            mma_tf32(acc[1][n], a1, bb);
        }
    }

    const float* X0 = xin + (size_t)cr0 * Dn;
    const float* X1 = xin + (size_t)cr1 * Dn;
    const float* X2 = xin + (size_t)cr2 * Dn;
    const float* X3 = xin + (size_t)cr3 * Dn;
#pragma unroll
    for (int ks = 0; ks < 8; ks++) {
        int ka = ks * 8 + 2 * q;
        float2 s0 = *reinterpret_cast<const float2*>(X0 + ka);
        float2 s1 = *reinterpret_cast<const float2*>(X1 + ka);
        float2 s2 = *reinterpret_cast<const float2*>(X2 + ka);
        float2 s3 = *reinterpret_cast<const float2*>(X3 + ka);
        unsigned a0[4] = { f2tf32(s0.x), f2tf32(s1.x), f2tf32(s0.y), f2tf32(s1.y) };
        unsigned a1[4] = { f2tf32(s2.x), f2tf32(s3.x), f2tf32(s2.y), f2tf32(s3.y) };
        const unsigned* w0 = sw + (256 + ka) * BSTR + g;
#pragma unroll
        for (int n = 0; n < 8; n++) {
            unsigned bb[2] = { w0[n * 8], w0[BSTR + n * 8] };
            mma_tf32(acc[0][n], a0, bb);
            mma_tf32(acc[1][n], a1, bb);
        }
    }

#pragma unroll
    for (int n = 0; n < 8; n++) {
        int col = n * 8 + 2 * q;
        float b0v = sb[col], b1v = sb[col + 1];
        if (r0 < N) {
            float2 o = { sigmoidf_(acc[0][n][0] + b0v), sigmoidf_(acc[0][n][1] + b1v) };
            *reinterpret_cast<float2*>(out + (size_t)r0 * Dn + col) = o;
        }
        if (r1 < N) {
            float2 o = { sigmoidf_(acc[0][n][2] + b0v), sigmoidf_(acc[0][n][3] + b1v) };
            *reinterpret_cast<float2*>(out + (size_t)r1 * Dn + col) = o;
        }
        if (r2 < N) {
            float2 o = { sigmoidf_(acc[1][n][0] + b0v), sigmoidf_(acc[1][n][1] + b1v) };
            *reinterpret_cast<float2*>(out + (size_t)r2 * Dn + col) = o;
        }
        if (r3 < N) {
            float2 o = { sigmoidf_(acc[1][n][2] + b0v), sigmoidf_(acc[1][n][3] + b1v) };
            *reinterpret_cast<float2*>(out + (size_t)r3 * Dn + col) = o;
        }
    }
}

// ---------------- highway via tf32 mma ----------------
// 256 threads / 8 warps, 16 nodes per warp -> 128 nodes per block.
// Optionally dual-writes a bf16 mirror of the output (gather path for next layer).
__global__ void __launch_bounds__(256)
highway_mma_kernel(const float* __restrict__ h,
                   const float* __restrict__ prev,
                   const float* __restrict__ pw,   // [64][128]
                   const float* __restrict__ pb,
                   const float* __restrict__ tw,   // [64][128]
                   const float* __restrict__ tb,
                   float* __restrict__ out,
                   __nv_bfloat162* __restrict__ outb,
                   int N) {
    extern __shared__ unsigned smu[];
    unsigned* sp = smu;                            // 128 * BSTR
    unsigned* st = sp + 128 * BSTR;                // 128 * BSTR
    float* sbp = (float*)(st + 128 * BSTR);        // 64
    float* sbt = sbp + Dn;                         // 64
    int tid = threadIdx.x;

    for (int idx = tid; idx < Dn * 128; idx += 256) {
        int j = idx >> 7, k = idx & 127;
        sp[k * BSTR + j] = f2tf32(pw[idx]);
        st[k * BSTR + j] = f2tf32(tw[idx]);
    }
    if (tid < Dn) { sbp[tid] = pb[tid]; sbt[tid] = tb[tid]; }
    __syncthreads();

    int lane = tid & 31, warp = tid >> 5;
    int g = lane >> 2, q = lane & 3;
    int mbase = blockIdx.x * 128 + warp * 16;

    int r0 = mbase + g, r1 = r0 + 8;
    int cr0 = min(r0, N - 1), cr1 = min(r1, N - 1);

    float accP[8][4], accT[8][4];
#pragma unroll
    for (int n = 0; n < 8; n++)
#pragma unroll
        for (int i = 0; i < 4; i++) { accP[n][i] = 0.f; accT[n][i] = 0.f; }

    const float* H0 = h + (size_t)cr0 * Dn;
    const float* H1 = h + (size_t)cr1 * Dn;
    const float* P0 = prev + (size_t)cr0 * Dn;
    const float* P1 = prev + (size_t)cr1 * Dn;

#pragma unroll
    for (int ks = 0; ks < 8; ks++) {
        int ka = ks * 8 + 2 * q;
        float2 s0 = *reinterpret_cast<const float2*>(H0 + ka);
        float2 s1 = *reinterpret_cast<const float2*>(H1 + ka);
        unsigned a[4] = { f2tf32(s0.x), f2tf32(s1.x), f2tf32(s0.y), f2tf32(s1.y) };
        const unsigned* p0 = sp + ka * BSTR + g;
        const unsigned* t0 = st + ka * BSTR + g;
#pragma unroll
        for (int n = 0; n < 8; n++) {
            unsigned bp[2] = { p0[n * 8], p0[BSTR + n * 8] };
            unsigned bt[2] = { t0[n * 8], t0[BSTR + n * 8] };
            mma_tf32(accP[n], a, bp);
            mma_tf32(accT[n], a, bt);
        }
    }
#pragma unroll
    for (int ks = 0; ks < 8; ks++) {
        int ka = ks * 8 + 2 * q;
        float2 s0 = *reinterpret_cast<const float2*>(P0 + ka);
        float2 s1 = *reinterpret_cast<const float2*>(P1 + ka);
        unsigned a[4] = { f2tf32(s0.x), f2tf32(s1.x), f2tf32(s0.y), f2tf32(s1.y) };
        const unsigned* p0 = sp + (64 + ka) * BSTR + g;
        const unsigned* t0 = st + (64 + ka) * BSTR + g;
#pragma unroll
        for (int n = 0; n < 8; n++) {
            unsigned bp[2] = { p0[n * 8], p0[BSTR + n * 8] };
            unsigned bt[2] = { t0[n * 8], t0[BSTR + n * 8] };
            mma_tf32(accP[n], a, bp);
            mma_tf32(accT[n], a, bt);
        }
    }

#pragma unroll
    for (int n = 0; n < 8; n++) {
        int col = n * 8 + 2 * q;
        float bp0 = sbp[col], bp1 = sbp[col + 1];
        float bt0 = sbt[col], bt1 = sbt[col + 1];
        if (r0 < N) {
            float2 hv = *reinterpret_cast<const float2*>(h + (size_t)r0 * Dn + col);
            float pr0 = fmaxf(accP[n][0] + bp0, 0.f);
            float pr1 = fmaxf(accP[n][1] + bp1, 0.f);
            float g0 = sigmoidf_(accT[n][0] + bt0);
            float g1 = sigmoidf_(accT[n][1] + bt1);
            float2 o = { g0 * pr0 + (1.f - g0) * hv.x, g1 * pr1 + (1.f - g1) * hv.y };
            *reinterpret_cast<float2*>(out + (size_t)r0 * Dn + col) = o;
            if (outb) outb[((size_t)r0 * Dn + col) >> 1] = __float22bfloat162_rn(o);
        }
        if (r1 < N) {
            float2 hv = *reinterpret_cast<const float2*>(h + (size_t)r1 * Dn + col);
            float pr0 = fmaxf(accP[n][2] + bp0, 0.f);
            float pr1 = fmaxf(accP[n][3] + bp1, 0.f);
            float g0 = sigmoidf_(accT[n][2] + bt0);
            float g1 = sigmoidf_(accT[n][3] + bt1);
            float2 o = { g0 * pr0 + (1.f - g0) * hv.x, g1 * pr1 + (1.f - g1) * hv.y };
            *reinterpret_cast<float2*>(out + (size_t)r1 * Dn + col) = o;
            if (outb) outb[((size_t)r1 * Dn + col) >> 1] = __float22bfloat162_rn(o);
        }
    }
}

// ---------------- launch ----------------
extern "C" void kernel_launch(void* const* d_in, const int* in_sizes, int n_in,
                              void* d_out, int out_size) {
    const float* x    = (const float*)d_in[0];
    const int*   src  = (const int*)d_in[1];
    const int*   dst  = (const int*)d_in[2];
    const int*   rel  = (const int*)d_in[3];
    const float* c1w  = (const float*)d_in[4];
    const float* c1b  = (const float*)d_in[5];
    const float* c1ws = (const float*)d_in[6];
    const float* c1bs = (const float*)d_in[7];
    const float* h1pw = (const float*)d_in[8];
    const float* h1pb = (const float*)d_in[9];
    const float* h1tw = (const float*)d_in[10];
    const float* h1tb = (const float*)d_in[11];
    const float* c2w  = (const float*)d_in[12];
    const float* c2b  = (const float*)d_in[13];
    const float* c2ws = (const float*)d_in[14];
    const float* c2bs = (const float*)d_in[15];
    const float* h2pw = (const float*)d_in[16];
    const float* h2pb = (const float*)d_in[17];
    const float* h2tw = (const float*)d_in[18];
    const float* h2tb = (const float*)d_in[19];
    float* out = (float*)d_out;

    int N = in_sizes[0] / Dn;
    int E = in_sizes[1];

    __nv_bfloat162 *Sp, *xbp, *g1bp;
    float *h1p, *g1p, *h2p;
    cudaGetSymbolAddress((void**)&Sp, g_S);
    cudaGetSymbolAddress((void**)&xbp, g_xb);
    cudaGetSymbolAddress((void**)&g1bp, g_g1b);
    cudaGetSymbolAddress((void**)&h1p, g_h1);
    cudaGetSymbolAddress((void**)&g1p, g_g1);
    cudaGetSymbolAddress((void**)&h2p, g_h2);

    const int convSmem = 320 * BSTR * 4 + 64 * 4;
    const int hwSmem   = 2 * 128 * BSTR * 4 + 128 * 4;
    cudaFuncSetAttribute(conv_mma_kernel, cudaFuncAttributeMaxDynamicSharedMemorySize, convSmem);
    cudaFuncSetAttribute(highway_mma_kernel, cudaFuncAttributeMaxDynamicSharedMemorySize, hwSmem);

    int convGrid = (N + 255) / 256;
    int hwGrid   = (N + 127) / 128;
    int scanBlocks = (SEGS + 1023) / 1024;

    // ---- bf16 mirror of x + CSR build (graph identical in both layers) ----
    f2b_kernel<<<(N * 32 + 255) / 256, 256>>>(x, xbp, N * 32);
    zero_deg_kernel<<<(SEGS + 255) / 256, 256>>>();
    hist_kernel<<<(E + 255) / 256, 256>>>(dst, rel, E);
    scan1_kernel<<<scanBlocks, 1024>>>(SEGS);
    scan2_kernel<<<1, 512>>>(scanBlocks);
    scan3_kernel<<<(SEGS + 255) / 256, 256>>>(SEGS, E);
    scatter_kernel<<<(E + 255) / 256, 256>>>(src, dst, rel, E);

    int aggGrid = SEGS / 32;   // 8 lanes per segment

    // ---- layer 1 ----
    aggregate_kernel<<<aggGrid, 256>>>(xbp);
    conv_mma_kernel<<<convGrid, 256, convSmem>>>(x, Sp, c1w, c1b, c1ws, c1bs, h1p, N);
    highway_mma_kernel<<<hwGrid, 256, hwSmem>>>(h1p, x, h1pw, h1pb, h1tw, h1tb, g1p, g1bp, N);

    // ---- layer 2 ----
    aggregate_kernel<<<aggGrid, 256>>>(g1bp);
    conv_mma_kernel<<<convGrid, 256, convSmem>>>(g1p, Sp, c2w, c2b, c2ws, c2bs, h2p, N);
    highway_mma_kernel<<<hwGrid, 256, hwSmem>>>(h2p, h1p, h2pw, h2pb, h2tw, h2tb, out, nullptr, N);
}

// round 11
// speedup vs baseline: 1.3023x; 1.2278x over previous
#include <cuda_runtime.h>
#include <cuda_bf16.h>
#include <math.h>

#define Dn   64
#define Rn   4
#define NMAX 100000
#define EMAX 1200000
#define SEGS (NMAX * Rn)
#define BSTR 68   // weight pair-row stride: banks (2q*68 + g)%32 = 8q+g -> conflict-free

// ---------------- scratch ----------------
__device__ int   g_deg[SEGS];
__device__ int   g_off[SEGS + 1];
__device__ int   g_cur[SEGS];
__device__ int   g_srcs[EMAX];
__device__ int   g_part[512];
__device__ __nv_bfloat162 g_S[(size_t)SEGS * (Dn / 2)];   // per-(node,rel) MEAN, bf16
__device__ __nv_bfloat162 g_xb[(size_t)NMAX * (Dn / 2)];  // bf16 mirror of x
__device__ __nv_bfloat162 g_h1b[(size_t)NMAX * (Dn / 2)]; // bf16 mirror of h1
__device__ __nv_bfloat162 g_g1b[(size_t)NMAX * (Dn / 2)]; // bf16 mirror of g1
__device__ __nv_bfloat162 g_h2b[(size_t)NMAX * (Dn / 2)]; // bf16 mirror of h2
__device__ float g_h1[(size_t)NMAX * Dn];
__device__ float g_g1[(size_t)NMAX * Dn];
__device__ float g_h2[(size_t)NMAX * Dn];

__device__ __forceinline__ float sigmoidf_(float v) {
    return 1.0f / (1.0f + __expf(-v));
}

__device__ __forceinline__ float2 b2f2(unsigned u) {
    __nv_bfloat162 t = *reinterpret_cast<__nv_bfloat162*>(&u);
    return __bfloat1622float2(t);
}

__device__ __forceinline__ unsigned packbf(float lo, float hi) {
    __nv_bfloat162 t = __float22bfloat162_rn(make_float2(lo, hi));
    return *reinterpret_cast<unsigned*>(&t);
}

__device__ __forceinline__ void mma_bf16(float d[4], const unsigned a[4], const unsigned b[2]) {
    asm volatile("mma.sync.aligned.m16n8k16.row.col.f32.bf16.bf16.f32 "
                 "{%0,%1,%2,%3}, {%4,%5,%6,%7}, {%8,%9}, {%0,%1,%2,%3};"
                 : "+f"(d[0]), "+f"(d[1]), "+f"(d[2]), "+f"(d[3])
                 : "r"(a[0]), "r"(a[1]), "r"(a[2]), "r"(a[3]), "r"(b[0]), "r"(b[1]));
}

// ---------------- fp32 -> bf16x2 mirror ----------------
__global__ void f2b_kernel(const float* __restrict__ in, __nv_bfloat162* __restrict__ out, int n2) {
    int i = blockIdx.x * 256 + threadIdx.x;
    if (i < n2) {
        float2 v = reinterpret_cast<const float2*>(in)[i];
        out[i] = __float22bfloat162_rn(v);
    }
}

// ---------------- CSR build ----------------
__global__ void zero_deg_kernel() {
    int i = blockIdx.x * blockDim.x + threadIdx.x;
    if (i < SEGS) g_deg[i] = 0;
}

__global__ void hist_kernel(const int* __restrict__ dst, const int* __restrict__ rel, int E) {
    int e = blockIdx.x * blockDim.x + threadIdx.x;
    if (e < E) atomicAdd(&g_deg[dst[e] * Rn + rel[e]], 1);
}

__global__ void __launch_bounds__(1024) scan1_kernel(int n) {
    __shared__ int wsum[32];
    int i = blockIdx.x * 1024 + threadIdx.x;
    int lane = threadIdx.x & 31, wid = threadIdx.x >> 5;
    int v = (i < n) ? g_deg[i] : 0;
    int s = v;
#pragma unroll
    for (int d = 1; d < 32; d <<= 1) {
        int t = __shfl_up_sync(0xffffffffu, s, d);
        if (lane >= d) s += t;
    }
    if (lane == 31) wsum[wid] = s;
    __syncthreads();
    if (wid == 0) {
        int t = wsum[lane];
#pragma unroll
        for (int d = 1; d < 32; d <<= 1) {
            int u = __shfl_up_sync(0xffffffffu, t, d);
            if (lane >= d) t += u;
        }
        wsum[lane] = t;
    }
    __syncthreads();
    int add = (wid > 0) ? wsum[wid - 1] : 0;
    int inc = s + add;
    if (i < n) g_off[i] = inc - v;
    if (threadIdx.x == 1023) g_part[blockIdx.x] = inc;
}

__global__ void __launch_bounds__(512) scan2_kernel(int n) {
    __shared__ int wsum[16];
    int i = threadIdx.x;
    int lane = i & 31, wid = i >> 5;
    int v = (i < n) ? g_part[i] : 0;
    int s = v;
#pragma unroll
    for (int d = 1; d < 32; d <<= 1) {
        int t = __shfl_up_sync(0xffffffffu, s, d);
        if (lane >= d) s += t;
    }
    if (lane == 31) wsum[wid] = s;
    __syncthreads();
    if (wid == 0 && lane < 16) {
        int t = wsum[lane];
#pragma unroll
        for (int d = 1; d < 16; d <<= 1) {
            int u = __shfl_up_sync(0x0000ffffu, t, d);
            if (lane >= d) t += u;
        }
        wsum[lane] = t;
    }
    __syncthreads();
    int add = (wid > 0) ? wsum[wid - 1] : 0;
    if (i < n) g_part[i] = s - v + add;
}

__global__ void scan3_kernel(int n, int E) {
    int i = blockIdx.x * blockDim.x + threadIdx.x;
    if (i < n) {
        int o = g_off[i] + g_part[i >> 10];
        g_off[i] = o;
        g_cur[i] = o;
    }
    if (i == 0) g_off[n] = E;
}

__global__ void scatter_kernel(const int* __restrict__ src, const int* __restrict__ dst,
                               const int* __restrict__ rel, int E) {
    int e = blockIdx.x * blockDim.x + threadIdx.x;
    if (e >= E) return;
    int seg = dst[e] * Rn + rel[e];
    int p = atomicAdd(&g_cur[seg], 1);
    g_srcs[p] = src[e];
}

// ---------------- aggregate: S[seg] = MEAN over edges of xb[src] ----------------
// 8 lanes per segment, uint4 (16B = 8 bf16) per lane.
__global__ void __launch_bounds__(256) aggregate_kernel(const __nv_bfloat162* __restrict__ xb) {
    int t = blockIdx.x * 256 + threadIdx.x;
    int seg = t >> 3;
    int lane = t & 7;
    if (seg >= SEGS) return;
    const uint4* rows = reinterpret_cast<const uint4*>(xb);
    int e0 = __ldg(&g_off[seg]);
    int e1 = __ldg(&g_off[seg + 1]);
    float a0 = 0.f, a1 = 0.f, a2 = 0.f, a3 = 0.f;
    float a4 = 0.f, a5 = 0.f, a6 = 0.f, a7 = 0.f;
    int e = e0;
    for (; e + 3 < e1; e += 4) {
        int s0 = __ldg(&g_srcs[e]);
        int s1 = __ldg(&g_srcs[e + 1]);
        int s2 = __ldg(&g_srcs[e + 2]);
        int s3 = __ldg(&g_srcs[e + 3]);
        uint4 u0 = __ldg(&rows[(size_t)s0 * 8 + lane]);
        uint4 u1 = __ldg(&rows[(size_t)s1 * 8 + lane]);
        uint4 u2 = __ldg(&rows[(size_t)s2 * 8 + lane]);
        uint4 u3 = __ldg(&rows[(size_t)s3 * 8 + lane]);
        float2 p;
        p = b2f2(u0.x); a0 += p.x; a1 += p.y;
        p = b2f2(u0.y); a2 += p.x; a3 += p.y;
        p = b2f2(u0.z); a4 += p.x; a5 += p.y;
        p = b2f2(u0.w); a6 += p.x; a7 += p.y;
        p = b2f2(u1.x); a0 += p.x; a1 += p.y;
        p = b2f2(u1.y); a2 += p.x; a3 += p.y;
        p = b2f2(u1.z); a4 += p.x; a5 += p.y;
        p = b2f2(u1.w); a6 += p.x; a7 += p.y;
        p = b2f2(u2.x); a0 += p.x; a1 += p.y;
        p = b2f2(u2.y); a2 += p.x; a3 += p.y;
        p = b2f2(u2.z); a4 += p.x; a5 += p.y;
        p = b2f2(u2.w); a6 += p.x; a7 += p.y;
        p = b2f2(u3.x); a0 += p.x; a1 += p.y;
        p = b2f2(u3.y); a2 += p.x; a3 += p.y;
        p = b2f2(u3.z); a4 += p.x; a5 += p.y;
        p = b2f2(u3.w); a6 += p.x; a7 += p.y;
    }
    for (; e < e1; e++) {
        int s0 = __ldg(&g_srcs[e]);
        uint4 u0 = __ldg(&rows[(size_t)s0 * 8 + lane]);
        float2 p;
        p = b2f2(u0.x); a0 += p.x; a1 += p.y;
        p = b2f2(u0.y); a2 += p.x; a3 += p.y;
        p = b2f2(u0.z); a4 += p.x; a5 += p.y;
        p = b2f2(u0.w); a6 += p.x; a7 += p.y;
    }
    int d = e1 - e0;
    float inv = 1.0f / (float)(d > 1 ? d : 1);
    uint4 o;
    o.x = packbf(a0 * inv, a1 * inv);
    o.y = packbf(a2 * inv, a3 * inv);
    o.z = packbf(a4 * inv, a5 * inv);
    o.w = packbf(a6 * inv, a7 * inv);
    reinterpret_cast<uint4*>(g_S)[(size_t)seg * 8 + lane] = o;
}

// ---------------- conv via bf16 m16n8k16 mma ----------------
// 256 threads / 8 warps, 32 nodes per warp -> 256 nodes per block.
// 4-per-lane k-permutation: logical frag k {2q,2q+1,2q+8,2q+9} <-> actual {4q..4q+3}.
__global__ void __launch_bounds__(256)
conv_mma_kernel(const __nv_bfloat162* __restrict__ xb,
                const __nv_bfloat162* __restrict__ S,
                const float* __restrict__ w,   // [64][256]
                const float* __restrict__ b,
                const float* __restrict__ ws,  // [64][64]
                const float* __restrict__ bs,
                float* __restrict__ out,
                __nv_bfloat162* __restrict__ outb,
                int N) {
    extern __shared__ unsigned smu[];
    unsigned* sw = smu;                           // 160 pair-rows * BSTR
    float* sb = (float*)(smu + 160 * BSTR);       // 64
    int tid = threadIdx.x;

    // stage weights as bf16x2 pair-rows: sw[kp][j] = {w[j][2kp], w[j][2kp+1]}
    for (int idx = tid; idx < Dn * 128; idx += 256) {
        int j = idx >> 7, kp = idx & 127;
        float2 v = *reinterpret_cast<const float2*>(w + j * 256 + 2 * kp);
        sw[kp * BSTR + j] = packbf(v.x, v.y);
    }
    for (int idx = tid; idx < Dn * 32; idx += 256) {
        int j = idx >> 5, kp = idx & 31;
        float2 v = *reinterpret_cast<const float2*>(ws + j * 64 + 2 * kp);
        sw[(128 + kp) * BSTR + j] = packbf(v.x, v.y);
    }
    if (tid < Dn) sb[tid] = b[tid] + bs[tid];
    __syncthreads();

    int lane = tid & 31, warp = tid >> 5;
    int g = lane >> 2, q = lane & 3;
    int mbase = blockIdx.x * 256 + warp * 32;

    int r0 = mbase + g, r1 = r0 + 8, r2 = r0 + 16, r3 = r0 + 24;
    int cr0 = min(r0, N - 1), cr1 = min(r1, N - 1);
    int cr2 = min(r2, N - 1), cr3 = min(r3, N - 1);

    float acc[2][8][4];
#pragma unroll
    for (int mt = 0; mt < 2; mt++)
#pragma unroll
        for (int n = 0; n < 8; n++)
#pragma unroll
            for (int i = 0; i < 4; i++) acc[mt][n][i] = 0.f;

    const uint2* S0 = reinterpret_cast<const uint2*>(S + (size_t)cr0 * 128);
    const uint2* S1 = reinterpret_cast<const uint2*>(S + (size_t)cr1 * 128);
    const uint2* S2 = reinterpret_cast<const uint2*>(S + (size_t)cr2 * 128);
    const uint2* S3 = reinterpret_cast<const uint2*>(S + (size_t)cr3 * 128);

#pragma unroll 2
    for (int kw = 0; kw < 16; kw++) {
        int ui = kw * 4 + q;
        uint2 U0 = S0[ui], U1 = S1[ui], U2 = S2[ui], U3 = S3[ui];
        unsigned a0[4] = { U0.x, U1.x, U0.y, U1.y };
        unsigned a1[4] = { U2.x, U3.x, U2.y, U3.y };
        const unsigned* w0 = sw + (kw * 8 + 2 * q) * BSTR + g;
#pragma unroll
        for (int n = 0; n < 8; n++) {
            unsigned bb[2] = { w0[n * 8], w0[BSTR + n * 8] };
            mma_bf16(acc[0][n], a0, bb);
            mma_bf16(acc[1][n], a1, bb);
        }
    }

    const uint2* X0 = reinterpret_cast<const uint2*>(xb + (size_t)cr0 * 32);
    const uint2* X1 = reinterpret_cast<const uint2*>(xb + (size_t)cr1 * 32);
    const uint2* X2 = reinterpret_cast<const uint2*>(xb + (size_t)cr2 * 32);
    const uint2* X3 = reinterpret_cast<const uint2*>(xb + (size_t)cr3 * 32);
#pragma unroll
    for (int kw = 0; kw < 4; kw++) {
        int ui = kw * 4 + q;
        uint2 U0 = X0[ui], U1 = X1[ui], U2 = X2[ui], U3 = X3[ui];
        unsigned a0[4] = { U0.x, U1.x, U0.y, U1.y };
        unsigned a1[4] = { U2.x, U3.x, U2.y, U3.y };
        const unsigned* w0 = sw + (128 + kw * 8 + 2 * q) * BSTR + g;
#pragma unroll
        for (int n = 0; n < 8; n++) {
            unsigned bb[2] = { w0[n * 8], w0[BSTR + n * 8] };
            mma_bf16(acc[0][n], a0, bb);
            mma_bf16(acc[1][n], a1, bb);
        }
    }

#pragma unroll
    for (int n = 0; n < 8; n++) {
        int col = n * 8 + 2 * q;
        float b0v = sb[col], b1v = sb[col + 1];
        if (r0 < N) {
            float2 o = { sigmoidf_(acc[0][n][0] + b0v), sigmoidf_(acc[0][n][1] + b1v) };
            *reinterpret_cast<float2*>(out + (size_t)r0 * Dn + col) = o;
            outb[((size_t)r0 * Dn + col) >> 1] = __float22bfloat162_rn(o);
        }
        if (r1 < N) {
            float2 o = { sigmoidf_(acc[0][n][2] + b0v), sigmoidf_(acc[0][n][3] + b1v) };
            *reinterpret_cast<float2*>(out + (size_t)r1 * Dn + col) = o;
            outb[((size_t)r1 * Dn + col) >> 1] = __float22bfloat162_rn(o);
        }
        if (r2 < N) {
            float2 o = { sigmoidf_(acc[1][n][0] + b0v), sigmoidf_(acc[1][n][1] + b1v) };
            *reinterpret_cast<float2*>(out + (size_t)r2 * Dn + col) = o;
            outb[((size_t)r2 * Dn + col) >> 1] = __float22bfloat162_rn(o);
        }
        if (r3 < N) {
            float2 o = { sigmoidf_(acc[1][n][2] + b0v), sigmoidf_(acc[1][n][3] + b1v) };
            *reinterpret_cast<float2*>(out + (size_t)r3 * Dn + col) = o;
            outb[((size_t)r3 * Dn + col) >> 1] = __float22bfloat162_rn(o);
        }
    }
}

// ---------------- highway via bf16 m16n8k16 mma ----------------
// 256 threads / 8 warps, 16 nodes per warp -> 128 nodes per block.
// A-frags from bf16 mirrors; final blend reads fp32 h for precision.
__global__ void __launch_bounds__(256)
highway_mma_kernel(const float* __restrict__ h,
                   const __nv_bfloat162* __restrict__ hb,
                   const __nv_bfloat162* __restrict__ prevb,
                   const float* __restrict__ pw,   // [64][128]
                   const float* __restrict__ pb,
                   const float* __restrict__ tw,   // [64][128]
                   const float* __restrict__ tb,
                   float* __restrict__ out,
                   __nv_bfloat162* __restrict__ outb,
                   int N) {
    extern __shared__ unsigned smu[];
    unsigned* sp = smu;                            // 64 pair-rows * BSTR
    unsigned* st = sp + 64 * BSTR;                 // 64 pair-rows * BSTR
    float* sbp = (float*)(st + 64 * BSTR);         // 64
    float* sbt = sbp + Dn;                         // 64
    int tid = threadIdx.x;

    for (int idx = tid; idx < Dn * 64; idx += 256) {
        int j = idx >> 6, kp = idx & 63;
        float2 vp = *reinterpret_cast<const float2*>(pw + j * 128 + 2 * kp);
        float2 vt = *reinterpret_cast<const float2*>(tw + j * 128 + 2 * kp);
        sp[kp * BSTR + j] = packbf(vp.x, vp.y);
        st[kp * BSTR + j] = packbf(vt.x, vt.y);
    }
    if (tid < Dn) { sbp[tid] = pb[tid]; sbt[tid] = tb[tid]; }
    __syncthreads();

    int lane = tid & 31, warp = tid >> 5;
    int g = lane >> 2, q = lane & 3;
    int mbase = blockIdx.x * 128 + warp * 16;

    int r0 = mbase + g, r1 = r0 + 8;
    int cr0 = min(r0, N - 1), cr1 = min(r1, N - 1);

    float accP[8][4], accT[8][4];
#pragma unroll
    for (int n = 0; n < 8; n++)
#pragma unroll
        for (int i = 0; i < 4; i++) { accP[n][i] = 0.f; accT[n][i] = 0.f; }

    const uint2* H0 = reinterpret_cast<const uint2*>(hb + (size_t)cr0 * 32);
    const uint2* H1 = reinterpret_cast<const uint2*>(hb + (size_t)cr1 * 32);
    const uint2* P0 = reinterpret_cast<const uint2*>(prevb + (size_t)cr0 * 32);
    const uint2* P1 = reinterpret_cast<const uint2*>(prevb + (size_t)cr1 * 32);

#pragma unroll
    for (int kw = 0; kw < 4; kw++) {
        int ui = kw * 4 + q;
        uint2 U0 = H0[ui], U1 = H1[ui];
        unsigned a[4] = { U0.x, U1.x, U0.y, U1.y };
        const unsigned* p0 = sp + (kw * 8 + 2 * q) * BSTR + g;
        const unsigned* t0 = st + (kw * 8 + 2 * q) * BSTR + g;
#pragma unroll
        for (int n = 0; n < 8; n++) {
            unsigned bp[2] = { p0[n * 8], p0[BSTR + n * 8] };
            unsigned bt[2] = { t0[n * 8], t0[BSTR + n * 8] };
            mma_bf16(accP[n], a, bp);
            mma_bf16(accT[n], a, bt);
        }
    }
#pragma unroll
    for (int kw = 0; kw < 4; kw++) {
        int ui = kw * 4 + q;
        uint2 U0 = P0[ui], U1 = P1[ui];
        unsigned a[4] = { U0.x, U1.x, U0.y, U1.y };
        const unsigned* p0 = sp + (32 + kw * 8 + 2 * q) * BSTR + g;
        const unsigned* t0 = st + (32 + kw * 8 + 2 * q) * BSTR + g;
#pragma unroll
        for (int n = 0; n < 8; n++) {
            unsigned bp[2] = { p0[n * 8], p0[BSTR + n * 8] };
            unsigned bt[2] = { t0[n * 8], t0[BSTR + n * 8] };
            mma_bf16(accP[n], a, bp);
            mma_bf16(accT[n], a, bt);
        }
    }

#pragma unroll
    for (int n = 0; n < 8; n++) {
        int col = n * 8 + 2 * q;
        float bp0 = sbp[col], bp1 = sbp[col + 1];
        float bt0 = sbt[col], bt1 = sbt[col + 1];
        if (r0 < N) {
            float2 hv = *reinterpret_cast<const float2*>(h + (size_t)r0 * Dn + col);
            float pr0 = fmaxf(accP[n][0] + bp0, 0.f);
            float pr1 = fmaxf(accP[n][1] + bp1, 0.f);
            float g0 = sigmoidf_(accT[n][0] + bt0);
            float g1 = sigmoidf_(accT[n][1] + bt1);
            float2 o = { g0 * pr0 + (1.f - g0) * hv.x, g1 * pr1 + (1.f - g1) * hv.y };
            *reinterpret_cast<float2*>(out + (size_t)r0 * Dn + col) = o;
            if (outb) outb[((size_t)r0 * Dn + col) >> 1] = __float22bfloat162_rn(o);
        }
        if (r1 < N) {
            float2 hv = *reinterpret_cast<const float2*>(h + (size_t)r1 * Dn + col);
            float pr0 = fmaxf(accP[n][2] + bp0, 0.f);
            float pr1 = fmaxf(accP[n][3] + bp1, 0.f);
            float g0 = sigmoidf_(accT[n][2] + bt0);
            float g1 = sigmoidf_(accT[n][3] + bt1);
            float2 o = { g0 * pr0 + (1.f - g0) * hv.x, g1 * pr1 + (1.f - g1) * hv.y };
            *reinterpret_cast<float2*>(out + (size_t)r1 * Dn + col) = o;
            if (outb) outb[((size_t)r1 * Dn + col) >> 1] = __float22bfloat162_rn(o);
        }
    }
}

// ---------------- launch ----------------
extern "C" void kernel_launch(void* const* d_in, const int* in_sizes, int n_in,
                              void* d_out, int out_size) {
    const float* x    = (const float*)d_in[0];
    const int*   src  = (const int*)d_in[1];
    const int*   dst  = (const int*)d_in[2];
    const int*   rel  = (const int*)d_in[3];
    const float* c1w  = (const float*)d_in[4];
    const float* c1b  = (const float*)d_in[5];
    const float* c1ws = (const float*)d_in[6];
    const float* c1bs = (const float*)d_in[7];
    const float* h1pw = (const float*)d_in[8];
    const float* h1pb = (const float*)d_in[9];
    const float* h1tw = (const float*)d_in[10];
    const float* h1tb = (const float*)d_in[11];
    const float* c2w  = (const float*)d_in[12];
    const float* c2b  = (const float*)d_in[13];
    const float* c2ws = (const float*)d_in[14];
    const float* c2bs = (const float*)d_in[15];
    const float* h2pw = (const float*)d_in[16];
    const float* h2pb = (const float*)d_in[17];
    const float* h2tw = (const float*)d_in[18];
    const float* h2tb = (const float*)d_in[19];
    float* out = (float*)d_out;

    int N = in_sizes[0] / Dn;
    int E = in_sizes[1];

    __nv_bfloat162 *Sp, *xbp, *h1bp, *g1bp, *h2bp;
    float *h1p, *g1p, *h2p;
    cudaGetSymbolAddress((void**)&Sp, g_S);
    cudaGetSymbolAddress((void**)&xbp, g_xb);
    cudaGetSymbolAddress((void**)&h1bp, g_h1b);
    cudaGetSymbolAddress((void**)&g1bp, g_g1b);
    cudaGetSymbolAddress((void**)&h2bp, g_h2b);
    cudaGetSymbolAddress((void**)&h1p, g_h1);
    cudaGetSymbolAddress((void**)&g1p, g_g1);
    cudaGetSymbolAddress((void**)&h2p, g_h2);

    const int convSmem = 160 * BSTR * 4 + 64 * 4;
    const int hwSmem   = 2 * 64 * BSTR * 4 + 128 * 4;
    cudaFuncSetAttribute(conv_mma_kernel, cudaFuncAttributeMaxDynamicSharedMemorySize, convSmem);
    cudaFuncSetAttribute(highway_mma_kernel, cudaFuncAttributeMaxDynamicSharedMemorySize, hwSmem);

    int convGrid = (N + 255) / 256;
    int hwGrid   = (N + 127) / 128;
    int scanBlocks = (SEGS + 1023) / 1024;

    // ---- bf16 mirror of x + CSR build (graph identical in both layers) ----
    f2b_kernel<<<(N * 32 + 255) / 256, 256>>>(x, xbp, N * 32);
    zero_deg_kernel<<<(SEGS + 255) / 256, 256>>>();
    hist_kernel<<<(E + 255) / 256, 256>>>(dst, rel, E);
    scan1_kernel<<<scanBlocks, 1024>>>(SEGS);
    scan2_kernel<<<1, 512>>>(scanBlocks);
    scan3_kernel<<<(SEGS + 255) / 256, 256>>>(SEGS, E);
    scatter_kernel<<<(E + 255) / 256, 256>>>(src, dst, rel, E);

    int aggGrid = SEGS / 32;   // 8 lanes per segment

    // ---- layer 1 ----
    aggregate_kernel<<<aggGrid, 256>>>(xbp);
    conv_mma_kernel<<<convGrid, 256, convSmem>>>(xbp, Sp, c1w, c1b, c1ws, c1bs, h1p, h1bp, N);
    highway_mma_kernel<<<hwGrid, 256, hwSmem>>>(h1p, h1bp, xbp, h1pw, h1pb, h1tw, h1tb, g1p, g1bp, N);

    // ---- layer 2 ----
    aggregate_kernel<<<aggGrid, 256>>>(g1bp);
    conv_mma_kernel<<<convGrid, 256, convSmem>>>(g1bp, Sp, c2w, c2b, c2ws, c2bs, h2p, h2bp, N);
    highway_mma_kernel<<<hwGrid, 256, hwSmem>>>(h2p, h2bp, h1bp, h2pw, h2pb, h2tw, h2tb, out, nullptr, N);
}